// round 5
// baseline (speedup 1.0000x reference)
#include <cuda_runtime.h>
#include <cuda_bf16.h>
#include <cstdint>

#define DIM      256
#define SEQ_LEN  65536
#define NCHUNK   148
#define WARM     32

// SMEM: Tw blocked bf16x2 layout [32 blocks][256 rows][4 words] = 128KB,
// then xs[256] f32 state, wsum[8], went[8].
#define TW_WORDS  (32 * 256 * 4)
#define SMEM_BYTES (TW_WORDS * 4 + (DIM + 16) * 4)

__device__ __forceinline__ float bf_lo(uint32_t w) {
    return __uint_as_float(w << 16);
}
__device__ __forceinline__ float bf_hi(uint32_t w) {
    return __uint_as_float(w & 0xFFFF0000u);
}

__global__ __launch_bounds__(256, 1)
void prior_layer_kernel(const float* __restrict__ probs,
                        const float* __restrict__ T,
                        float* __restrict__ out)
{
    extern __shared__ unsigned char smem_raw[];
    uint32_t* Tw   = reinterpret_cast<uint32_t*>(smem_raw);
    float*    xs   = reinterpret_cast<float*>(smem_raw + TW_WORDS * 4);
    float*    wsum = xs + DIM;
    float*    went = wsum + 8;

    const int j    = threadIdx.x;
    const int lane = j & 31;
    const int warp = j >> 5;

    // ---- Load T (fp32, row-major) into blocked bf16x2 SMEM layout ----
    // word index idx = b*1024 + row*4 + k  holds bf16x2( T[row][8b+2k], T[row][8b+2k+1] )
    for (int idx = j; idx < TW_WORDS; idx += 256) {
        int k   = idx & 3;
        int row = (idx >> 2) & 255;
        int b   = idx >> 10;
        int i0  = b * 8 + k * 2;
        float a  = T[row * DIM + i0];
        float bb = T[row * DIM + i0 + 1];
        __nv_bfloat162 h = __floats2bfloat162_rn(a, bb);  // .x = a (lo), .y = bb (hi)
        Tw[idx] = *reinterpret_cast<uint32_t*>(&h);
    }

    xs[j] = 1.0f / 256.0f;
    __syncthreads();

    // ---- Chunk assignment: 120 chunks of 443 steps, 28 of 442 ----
    const int c     = blockIdx.x;
    const int start = c * 442 + min(c, 120);
    const int len   = 442 + (c < 120 ? 1 : 0);
    const int tw    = (c == 0) ? 0 : (start - WARM);
    const int tend  = start + len;

    const uint32_t* wrow = Tw + j * 4;

    for (int t = tw; t < tend; ++t) {
        // obs prob for this thread's row (LDG issued early; consumed after matvec)
        float pj = probs[(size_t)t * DIM + j];

        // ---- matvec: y_j = sum_i T[j][i] * xs[i] ----
        float a0 = 0.f, a1 = 0.f, a2 = 0.f, a3 = 0.f;
        #pragma unroll
        for (int b = 0; b < 32; ++b) {
            uint4 w = *reinterpret_cast<const uint4*>(wrow + b * 1024);
            const float4* xb = reinterpret_cast<const float4*>(xs + b * 8);
            float4 x0 = xb[0];
            float4 x1 = xb[1];
            a0 += bf_lo(w.x) * x0.x;  a1 += bf_hi(w.x) * x0.y;
            a2 += bf_lo(w.y) * x0.z;  a3 += bf_hi(w.y) * x0.w;
            a0 += bf_lo(w.z) * x1.x;  a1 += bf_hi(w.z) * x1.y;
            a2 += bf_lo(w.w) * x1.z;  a3 += bf_hi(w.w) * x1.w;
        }
        float v = ((a0 + a1) + (a2 + a3)) * pj;

        // ---- sum reduction for normalization ----
        float s = v;
        #pragma unroll
        for (int off = 16; off > 0; off >>= 1)
            s += __shfl_xor_sync(0xFFFFFFFFu, s, off);
        if (lane == 0) wsum[warp] = s;
        __syncthreads();   // also guarantees all matvec reads of xs are done

        float S = ((wsum[0] + wsum[1]) + (wsum[2] + wsum[3]))
                + ((wsum[4] + wsum[5]) + (wsum[6] + wsum[7]));
        float inv  = __fdividef(1.0f, S);
        float snew = v * inv;

        // entropy contribution
        float e = snew * __logf(snew + 1e-10f);
        #pragma unroll
        for (int off = 16; off > 0; off >>= 1)
            e += __shfl_xor_sync(0xFFFFFFFFu, e, off);
        if (lane == 0) went[warp] = e;

        xs[j] = snew;      // safe: barrier above ensured all reads finished
        __syncthreads();   // xs + went visible for next iteration / entropy sum

        if (t >= start) {
            out[(size_t)t * DIM + j] = snew;
            if (j == 0) {
                float E = ((went[0] + went[1]) + (went[2] + went[3]))
                        + ((went[4] + went[5]) + (went[6] + went[7]));
                out[(size_t)SEQ_LEN * DIM + t] = -E;
            }
        }
    }
}

extern "C" void kernel_launch(void* const* d_in, const int* in_sizes, int n_in,
                              void* d_out, int out_size)
{
    const float* probs = (const float*)d_in[0];          // (65536, 256)
    const float* T     = (const float*)d_in[1];          // (256, 256)
    float* out         = (float*)d_out;                  // 65536*256 probs, then 65536 entropy

    static bool attr_set = false;
    if (!attr_set) {
        cudaFuncSetAttribute(prior_layer_kernel,
                             cudaFuncAttributeMaxDynamicSharedMemorySize,
                             SMEM_BYTES);
        attr_set = true;
    }
    prior_layer_kernel<<<NCHUNK, 256, SMEM_BYTES>>>(probs, T, out);
}

// round 10
// speedup vs baseline: 7.2600x; 7.2600x over previous
#include <cuda_runtime.h>
#include <cuda_bf16.h>
#include <cstdint>

#define DIM      256
#define SEQ_LEN  65536
#define GRID     148
#define CPB      8                       // chunks per block (MMA N)
#define BASE_LEN 55
#define REM      416                     // 65536 = 1184*55 + 416 -> first 416 chunks len 56
#define WARM     32
#define STEPS    (BASE_LEN + 1 + WARM)   // 88

__device__ __forceinline__ uint32_t packbf(float x, float y) {
    __nv_bfloat162 h = __floats2bfloat162_rn(x, y);   // .x in low 16 bits
    return *reinterpret_cast<uint32_t*>(&h);
}

// m16n8k16 bf16 MMA, fp32 accumulate (baseline PTX, maps to HMMA on sm_103)
__device__ __forceinline__ void mma16816(float* d, const uint32_t* a,
                                         uint32_t b0, uint32_t b1) {
    asm volatile(
        "mma.sync.aligned.m16n8k16.row.col.f32.bf16.bf16.f32 "
        "{%0,%1,%2,%3}, {%4,%5,%6,%7}, {%8,%9}, {%0,%1,%2,%3};"
        : "+f"(d[0]), "+f"(d[1]), "+f"(d[2]), "+f"(d[3])
        : "r"(a[0]), "r"(a[1]), "r"(a[2]), "r"(a[3]), "r"(b0), "r"(b1));
}

__global__ __launch_bounds__(256, 1)
void prior_layer_hmma(const float* __restrict__ probs,
                      const float* __restrict__ T,
                      float* __restrict__ out)
{
    // X operand: Xb[n][k] bf16, k-stride padded to 264 -> B-frag LDS conflict-free
    __shared__ __align__(16) uint16_t Xb[CPB][264];
    __shared__ __align__(16) float    Y[DIM][10];    // v values, row-major (pad 10)
    __shared__ __align__(16) float    P[DIM][10];    // staged obs probs
    __shared__ float wsum[8][8];                     // [warp][chunk]
    __shared__ float esum[8][8];

    const int tid  = threadIdx.x;
    const int lane = tid & 31;
    const int w    = tid >> 5;
    const int g    = lane >> 2;    // fragment "group" (row / B-col index)
    const int c    = lane & 3;     // fragment quad-pair (col / k index)

    // ---- Preload A fragments: warp w owns T rows [32w, 32w+32), constant ----
    uint32_t ta[2][16][4];
    #pragma unroll
    for (int mt = 0; mt < 2; ++mt) {
        #pragma unroll
        for (int kt = 0; kt < 16; ++kt) {
            const int R = w * 32 + mt * 16 + g;
            const int K = kt * 16 + c * 2;
            float2 f0 = *reinterpret_cast<const float2*>(T + (size_t)R * DIM + K);
            float2 f2 = *reinterpret_cast<const float2*>(T + (size_t)R * DIM + K + 8);
            float2 f1 = *reinterpret_cast<const float2*>(T + (size_t)(R + 8) * DIM + K);
            float2 f3 = *reinterpret_cast<const float2*>(T + (size_t)(R + 8) * DIM + K + 8);
            ta[mt][kt][0] = packbf(f0.x, f0.y);
            ta[mt][kt][1] = packbf(f1.x, f1.y);
            ta[mt][kt][2] = packbf(f2.x, f2.y);
            ta[mt][kt][3] = packbf(f3.x, f3.y);
        }
    }

    // ---- X_0 = uniform 1/256 ----
    for (int i = tid; i < CPB * 264 / 2; i += 256)
        reinterpret_cast<uint32_t*>(&Xb[0][0])[i] = 0x3B803B80u;

    int tb[CPB];
    #pragma unroll
    for (int n = 0; n < CPB; ++n) {
        int gc = blockIdx.x * CPB + n;
        tb[n]  = gc * BASE_LEN + min(gc, REM) - WARM;
    }

    // prefetch obs for s=0
    float pv[CPB];
    #pragma unroll
    for (int n = 0; n < CPB; ++n) {
        int t = min(max(tb[n], 0), SEQ_LEN - 1);
        pv[n] = __ldg(probs + (size_t)t * DIM + tid);
    }

    __syncthreads();

    for (int s = 0; s < STEPS; ++s) {
        // prefetch next step's observations (hidden behind MMA chain)
        float pnx[CPB];
        #pragma unroll
        for (int n = 0; n < CPB; ++n) {
            int t = min(max(tb[n] + s + 1, 0), SEQ_LEN - 1);
            pnx[n] = __ldg(probs + (size_t)t * DIM + tid);
        }

        // ---- D = T @ X : 32 HMMA, 2 independent chains (mt0 / mt1) ----
        float d[2][4] = {{0.f,0.f,0.f,0.f},{0.f,0.f,0.f,0.f}};
        #pragma unroll
        for (int kt = 0; kt < 16; ++kt) {
            uint32_t b0 = *reinterpret_cast<const uint32_t*>(&Xb[g][kt * 16 + c * 2]);
            uint32_t b1 = *reinterpret_cast<const uint32_t*>(&Xb[g][kt * 16 + c * 2 + 8]);
            mma16816(d[0], ta[0][kt], b0, b1);
            mma16816(d[1], ta[1][kt], b0, b1);
        }

        // stage observations to row-major SMEM
        #pragma unroll
        for (int n = 0; n < CPB; n += 2)
            *reinterpret_cast<float2*>(&P[tid][n]) = make_float2(pv[n], pv[n + 1]);

        __syncthreads();   // P visible; prev step's Y/wsum fully consumed

        // ---- fragment-space: v = D*p, fused sum + entropy-sum reduction ----
        float sv0 = 0.f, sv1 = 0.f, su0 = 0.f, su1 = 0.f;
        #pragma unroll
        for (int mt = 0; mt < 2; ++mt) {
            const int r = w * 32 + mt * 16 + g;
            float2 p0 = *reinterpret_cast<const float2*>(&P[r][c * 2]);
            float2 p1 = *reinterpret_cast<const float2*>(&P[r + 8][c * 2]);
            float v0 = d[mt][0] * p0.x;
            float v1 = d[mt][1] * p0.y;
            float v2 = d[mt][2] * p1.x;
            float v3 = d[mt][3] * p1.y;
            *reinterpret_cast<float2*>(&Y[r][c * 2])     = make_float2(v0, v1);
            *reinterpret_cast<float2*>(&Y[r + 8][c * 2]) = make_float2(v2, v3);
            sv0 += v0 + v2;  sv1 += v1 + v3;
            su0 += v0 * __logf(v0 + 1e-30f) + v2 * __logf(v2 + 1e-30f);
            su1 += v1 * __logf(v1 + 1e-30f) + v3 * __logf(v3 + 1e-30f);
        }
        #pragma unroll
        for (int off = 16; off >= 4; off >>= 1) {
            sv0 += __shfl_xor_sync(~0u, sv0, off);
            sv1 += __shfl_xor_sync(~0u, sv1, off);
            su0 += __shfl_xor_sync(~0u, su0, off);
            su1 += __shfl_xor_sync(~0u, su1, off);
        }
        if (lane < 4) {
            *reinterpret_cast<float2*>(&wsum[w][c * 2]) = make_float2(sv0, sv1);
            *reinterpret_cast<float2*>(&esum[w][c * 2]) = make_float2(su0, su1);
        }
        __syncthreads();   // wsum/esum/Y visible

        // ---- row-space epilogue ----
        float invl = 0.f, lSl = 0.f, Etl = 0.f;
        if (lane < 8) {
            float S = 0.f, E = 0.f;
            #pragma unroll
            for (int ww = 0; ww < 8; ++ww) { S += wsum[ww][lane]; E += esum[ww][lane]; }
            invl = __fdividef(1.0f, S);
            lSl  = __logf(S);
            Etl  = E;
        }
        float inb[CPB];
        #pragma unroll
        for (int n = 0; n < CPB; ++n) inb[n] = __shfl_sync(~0u, invl, n);

        float sn[CPB];
        #pragma unroll
        for (int n = 0; n < CPB; n += 2) {
            float2 t2 = *reinterpret_cast<const float2*>(&Y[tid][n]);
            sn[n]     = t2.x * inb[n];
            sn[n + 1] = t2.y * inb[n + 1];
        }

        if (s >= WARM) {
            #pragma unroll
            for (int n = 0; n < CPB; ++n) {
                int gc = blockIdx.x * CPB + n;
                int t  = tb[n] + s;
                int tl = tb[n] + WARM + BASE_LEN + (gc < REM ? 1 : 0);
                if (t < tl) out[(size_t)t * DIM + tid] = sn[n];
            }
            // entropy = log S - (sum v log v)/S  (exact rearrangement of -sum sn log sn)
            if (w == 1 && lane < 8) {
                int gc  = blockIdx.x * CPB + lane;
                int tbl = gc * BASE_LEN + min(gc, REM) - WARM;
                int t   = tbl + s;
                if (t < tbl + WARM + BASE_LEN + (gc < REM ? 1 : 0))
                    out[(size_t)SEQ_LEN * DIM + t] = lSl - Etl * invl;
            }
        }

        // chunk 0 has no real history: reset to uniform at warm/real boundary
        if (s == WARM - 1 && blockIdx.x == 0) sn[0] = 0.00390625f;

        // ---- write X_{s+1} ----
        #pragma unroll
        for (int n = 0; n < CPB; ++n)
            Xb[n][tid] = __bfloat16_as_ushort(__float2bfloat16(sn[n]));

        __syncthreads();   // X visible for next step's MMA

        #pragma unroll
        for (int n = 0; n < CPB; ++n) pv[n] = pnx[n];
    }
}

extern "C" void kernel_launch(void* const* d_in, const int* in_sizes, int n_in,
                              void* d_out, int out_size)
{
    const float* probs = (const float*)d_in[0];   // (65536, 256)
    const float* T     = (const float*)d_in[1];   // (256, 256)
    float* out         = (float*)d_out;           // 65536*256 probs, then 65536 entropy

    prior_layer_hmma<<<GRID, 256>>>(probs, T, out);
}

// round 12
// speedup vs baseline: 8.1372x; 1.1208x over previous
#include <cuda_runtime.h>
#include <cuda_bf16.h>
#include <cstdint>

#define DIM      256
#define SEQ_LEN  65536
#define GRID     148
#define CPB      8                       // chunks per block (MMA N)
#define BASE_LEN 55
#define REM      416                     // 65536 = 1184*55 + 416 -> first 416 chunks len 56
#define WARM     16
#define STEPS    (BASE_LEN + 1 + WARM)   // 72

__device__ __forceinline__ uint32_t packbf(float x, float y) {
    __nv_bfloat162 h = __floats2bfloat162_rn(x, y);   // .x in low 16 bits
    return *reinterpret_cast<uint32_t*>(&h);
}

// m16n8k16 bf16 MMA, fp32 accumulate (baseline PTX, maps to HMMA on sm_103)
__device__ __forceinline__ void mma16816(float* d, const uint32_t* a,
                                         uint32_t b0, uint32_t b1) {
    asm volatile(
        "mma.sync.aligned.m16n8k16.row.col.f32.bf16.bf16.f32 "
        "{%0,%1,%2,%3}, {%4,%5,%6,%7}, {%8,%9}, {%0,%1,%2,%3};"
        : "+f"(d[0]), "+f"(d[1]), "+f"(d[2]), "+f"(d[3])
        : "r"(a[0]), "r"(a[1]), "r"(a[2]), "r"(a[3]), "r"(b0), "r"(b1));
}

__global__ __launch_bounds__(256, 1)
void prior_layer_hmma(const float* __restrict__ probs,
                      const float* __restrict__ T,
                      float* __restrict__ out)
{
    // X operand: Xb[n][k] bf16, k-stride padded to 264 (16b) -> bank (4g+c), conflict-free
    __shared__ __align__(16) uint16_t Xb[CPB][264];
    // chunk-major f32 staging, stride 260 -> bank (4n + row) mod 32, conflict-free everywhere
    __shared__ float Y2[CPB][260];       // v values
    __shared__ float P2[2][CPB][260];    // double-buffered obs probs
    __shared__ float wsum[8][8];         // [warp][chunk]
    __shared__ float esum[8][8];

    const int tid  = threadIdx.x;
    const int lane = tid & 31;
    const int w    = tid >> 5;
    const int g    = lane >> 2;    // fragment row group / B-col index
    const int c    = lane & 3;     // fragment quad-pair / k index

    // ---- Preload A fragments: warp w owns T rows [32w, 32w+32), constant ----
    uint32_t ta[2][16][4];
    #pragma unroll
    for (int mt = 0; mt < 2; ++mt) {
        #pragma unroll
        for (int kt = 0; kt < 16; ++kt) {
            const int R = w * 32 + mt * 16 + g;
            const int K = kt * 16 + c * 2;
            float2 f0 = *reinterpret_cast<const float2*>(T + (size_t)R * DIM + K);
            float2 f2 = *reinterpret_cast<const float2*>(T + (size_t)R * DIM + K + 8);
            float2 f1 = *reinterpret_cast<const float2*>(T + (size_t)(R + 8) * DIM + K);
            float2 f3 = *reinterpret_cast<const float2*>(T + (size_t)(R + 8) * DIM + K + 8);
            ta[mt][kt][0] = packbf(f0.x, f0.y);
            ta[mt][kt][1] = packbf(f1.x, f1.y);
            ta[mt][kt][2] = packbf(f2.x, f2.y);
            ta[mt][kt][3] = packbf(f3.x, f3.y);
        }
    }

    // ---- X_0 = uniform 1/256 ----
    for (int i = tid; i < CPB * 264 / 2; i += 256)
        reinterpret_cast<uint32_t*>(&Xb[0][0])[i] = 0x3B803B80u;

    int tb[CPB];
    #pragma unroll
    for (int n = 0; n < CPB; ++n) {
        int gc = blockIdx.x * CPB + n;
        tb[n]  = gc * BASE_LEN + min(gc, REM) - WARM;
    }

    // stage P for s=0
    #pragma unroll
    for (int n = 0; n < CPB; ++n) {
        int t = min(max(tb[n], 0), SEQ_LEN - 1);
        P2[0][n][tid] = __ldg(probs + (size_t)t * DIM + tid);
    }

    __syncthreads();

    for (int s = 0; s < STEPS; ++s) {
        const int buf = s & 1;

        // prefetch next step's observations (landed by end of this step)
        float pnx[CPB];
        #pragma unroll
        for (int n = 0; n < CPB; ++n) {
            int t = min(max(tb[n] + s + 1, 0), SEQ_LEN - 1);
            pnx[n] = __ldg(probs + (size_t)t * DIM + tid);
        }

        // ---- D = T @ X : 32 HMMA / warp, 4 independent depth-8 chains ----
        float d[2][2][4] = {};
        #pragma unroll
        for (int kt = 0; kt < 8; ++kt) {
            uint32_t b0 = *reinterpret_cast<const uint32_t*>(&Xb[g][kt * 16 + c * 2]);
            uint32_t b1 = *reinterpret_cast<const uint32_t*>(&Xb[g][kt * 16 + c * 2 + 8]);
            uint32_t b2 = *reinterpret_cast<const uint32_t*>(&Xb[g][(kt + 8) * 16 + c * 2]);
            uint32_t b3 = *reinterpret_cast<const uint32_t*>(&Xb[g][(kt + 8) * 16 + c * 2 + 8]);
            mma16816(d[0][0], ta[0][kt], b0, b1);
            mma16816(d[1][0], ta[1][kt], b0, b1);
            mma16816(d[0][1], ta[0][kt + 8], b2, b3);
            mma16816(d[1][1], ta[1][kt + 8], b2, b3);
        }

        // ---- fragment-space: v = D*p, fused sum + entropy-sum reduction ----
        float sv0 = 0.f, sv1 = 0.f, su0 = 0.f, su1 = 0.f;
        #pragma unroll
        for (int mt = 0; mt < 2; ++mt) {
            const int r = w * 32 + mt * 16 + g;
            const int n0 = c * 2;
            float v0 = (d[mt][0][0] + d[mt][1][0]) * P2[buf][n0][r];
            float v1 = (d[mt][0][1] + d[mt][1][1]) * P2[buf][n0 + 1][r];
            float v2 = (d[mt][0][2] + d[mt][1][2]) * P2[buf][n0][r + 8];
            float v3 = (d[mt][0][3] + d[mt][1][3]) * P2[buf][n0 + 1][r + 8];
            Y2[n0][r]         = v0;
            Y2[n0 + 1][r]     = v1;
            Y2[n0][r + 8]     = v2;
            Y2[n0 + 1][r + 8] = v3;
            sv0 += v0 + v2;  sv1 += v1 + v3;
            su0 += v0 * __logf(v0 + 1e-30f) + v2 * __logf(v2 + 1e-30f);
            su1 += v1 * __logf(v1 + 1e-30f) + v3 * __logf(v3 + 1e-30f);
        }
        #pragma unroll
        for (int off = 16; off >= 4; off >>= 1) {
            sv0 += __shfl_xor_sync(~0u, sv0, off);
            sv1 += __shfl_xor_sync(~0u, sv1, off);
            su0 += __shfl_xor_sync(~0u, su0, off);
            su1 += __shfl_xor_sync(~0u, su1, off);
        }
        if (lane < 4) {
            *reinterpret_cast<float2*>(&wsum[w][c * 2]) = make_float2(sv0, sv1);
            *reinterpret_cast<float2*>(&esum[w][c * 2]) = make_float2(su0, su1);
        }
        __syncthreads();   // B1: wsum/esum/Y2 visible (P2[buf] reads done)

        // ---- row-space epilogue ----
        float invl = 0.f, lSl = 0.f, Etl = 0.f;
        if (lane < 8) {
            float S = 0.f, E = 0.f;
            #pragma unroll
            for (int ww = 0; ww < 8; ++ww) { S += wsum[ww][lane]; E += esum[ww][lane]; }
            invl = __fdividef(1.0f, S);
            lSl  = __logf(S);
            Etl  = E;
        }
        float inb[CPB];
        #pragma unroll
        for (int n = 0; n < CPB; ++n) inb[n] = __shfl_sync(~0u, invl, n);

        float sn[CPB];
        #pragma unroll
        for (int n = 0; n < CPB; ++n)
            sn[n] = Y2[n][tid] * inb[n];

        if (s >= WARM) {
            #pragma unroll
            for (int n = 0; n < CPB; ++n) {
                int gc = blockIdx.x * CPB + n;
                int t  = tb[n] + s;
                int tl = tb[n] + WARM + BASE_LEN + (gc < REM ? 1 : 0);
                if (t < tl) out[(size_t)t * DIM + tid] = sn[n];
            }
            // entropy = log S - (sum v log v)/S  (exact rearrangement of -sum sn log sn)
            if (w == 1 && lane < 8) {
                int gc  = blockIdx.x * CPB + lane;
                int tbl = gc * BASE_LEN + min(gc, REM) - WARM;
                int t   = tbl + s;
                if (t < tbl + WARM + BASE_LEN + (gc < REM ? 1 : 0))
                    out[(size_t)SEQ_LEN * DIM + t] = lSl - Etl * invl;
            }
        }

        // chunk 0 has no real history: reset to uniform at warm/real boundary
        if (s == WARM - 1 && blockIdx.x == 0) sn[0] = 0.00390625f;

        // ---- write X_{s+1} + stage P for next step ----
        #pragma unroll
        for (int n = 0; n < CPB; ++n) {
            Xb[n][tid] = __bfloat16_as_ushort(__float2bfloat16(sn[n]));
            P2[buf ^ 1][n][tid] = pnx[n];
        }

        __syncthreads();   // B2: Xb + P2[next] visible for next step
    }
}

extern "C" void kernel_launch(void* const* d_in, const int* in_sizes, int n_in,
                              void* d_out, int out_size)
{
    const float* probs = (const float*)d_in[0];   // (65536, 256)
    const float* T     = (const float*)d_in[1];   // (256, 256)
    float* out         = (float*)d_out;           // 65536*256 probs, then 65536 entropy

    prior_layer_hmma<<<GRID, 256>>>(probs, T, out);
}

// round 14
// speedup vs baseline: 9.1509x; 1.1246x over previous
#include <cuda_runtime.h>
#include <cuda_bf16.h>
#include <cstdint>

#define DIM      256
#define SEQ_LEN  65536
#define GRID     148
#define CPB      16                      // chunks per block (MMA N)
#define BASE_LEN 27
#define REM      1600                    // 65536 = 2368*27 + 1600 -> first 1600 chunks len 28
#define WARM     12
#define STEPS    (BASE_LEN + 1 + WARM)   // 40

__device__ __forceinline__ uint32_t packbf(float x, float y) {
    __nv_bfloat162 h = __floats2bfloat162_rn(x, y);   // .x in low 16 bits
    return *reinterpret_cast<uint32_t*>(&h);
}

// m16n8k16 bf16 MMA, fp32 accumulate (baseline PTX, maps to HMMA on sm_103)
__device__ __forceinline__ void mma16816(float* d, const uint32_t* a,
                                         uint32_t b0, uint32_t b1) {
    asm volatile(
        "mma.sync.aligned.m16n8k16.row.col.f32.bf16.bf16.f32 "
        "{%0,%1,%2,%3}, {%4,%5,%6,%7}, {%8,%9}, {%0,%1,%2,%3};"
        : "+f"(d[0]), "+f"(d[1]), "+f"(d[2]), "+f"(d[3])
        : "r"(a[0]), "r"(a[1]), "r"(a[2]), "r"(a[3]), "r"(b0), "r"(b1));
}

// chunk base time (start - WARM) for global chunk gc
__device__ __forceinline__ int chunk_tb(int gc) {
    return gc * BASE_LEN + min(gc, REM) - WARM;
}
__device__ __forceinline__ int chunk_tl(int gc) {   // exclusive end
    return gc * BASE_LEN + min(gc, REM) + BASE_LEN + (gc < REM ? 1 : 0);
}

__global__ __launch_bounds__(256, 1)
void prior_layer_hmma(const float* __restrict__ probs,
                      const float* __restrict__ T,
                      float* __restrict__ out)
{
    // X operand: Xb[n][k] bf16, k-stride padded to 264 -> conflict-free B-frag LDS
    __shared__ __align__(16) uint16_t Xb[CPB][264];
    // double-buffered obs probs, chunk-major, stride 260 -> bank (4n + r), conflict-free
    __shared__ float P2[2][CPB][260];
    __shared__ float wsum[8][CPB];       // [warp][chunk]
    __shared__ float esum[8][CPB];

    const int tid  = threadIdx.x;
    const int lane = tid & 31;
    const int w    = tid >> 5;
    const int g    = lane >> 2;    // fragment row group / B col index
    const int c    = lane & 3;     // fragment quad index (output cols 2c, 2c+1)

    // ---- Preload A fragments: warp w owns T rows [32w, 32w+32), constant ----
    uint32_t ta[2][16][4];
    #pragma unroll
    for (int mt = 0; mt < 2; ++mt) {
        #pragma unroll
        for (int kt = 0; kt < 16; ++kt) {
            const int R = w * 32 + mt * 16 + g;
            const int K = kt * 16 + c * 2;
            float2 f0 = *reinterpret_cast<const float2*>(T + (size_t)R * DIM + K);
            float2 f2 = *reinterpret_cast<const float2*>(T + (size_t)R * DIM + K + 8);
            float2 f1 = *reinterpret_cast<const float2*>(T + (size_t)(R + 8) * DIM + K);
            float2 f3 = *reinterpret_cast<const float2*>(T + (size_t)(R + 8) * DIM + K + 8);
            ta[mt][kt][0] = packbf(f0.x, f0.y);
            ta[mt][kt][1] = packbf(f1.x, f1.y);
            ta[mt][kt][2] = packbf(f2.x, f2.y);
            ta[mt][kt][3] = packbf(f3.x, f3.y);
        }
    }

    // ---- X_0 = uniform 1/256 ----
    for (int i = tid; i < CPB * 264 / 2; i += 256)
        reinterpret_cast<uint32_t*>(&Xb[0][0])[i] = 0x3B803B80u;

    const int gc0 = blockIdx.x * CPB;

    // stage P for s=0
    #pragma unroll
    for (int n = 0; n < CPB; ++n) {
        int t = min(max(chunk_tb(gc0 + n), 0), SEQ_LEN - 1);
        P2[0][n][tid] = __ldg(probs + (size_t)t * DIM + tid);
    }

    __syncthreads();

    for (int s = 0; s < STEPS; ++s) {
        const int buf = s & 1;

        // prefetch next step's observations (land during this step's compute)
        float pnx[CPB];
        #pragma unroll
        for (int n = 0; n < CPB; ++n) {
            int t = min(max(chunk_tb(gc0 + n) + s + 1, 0), SEQ_LEN - 1);
            pnx[n] = __ldg(probs + (size_t)t * DIM + tid);
        }

        // ---- D = T @ X : 64 HMMA / warp, 8 independent depth-8 chains ----
        // d[kc][mt][nt][4]; nt selects B cols (chunks) 8nt..8nt+7
        float d[2][2][2][4] = {};
        #pragma unroll
        for (int kt = 0; kt < 8; ++kt) {
            uint32_t b00 = *reinterpret_cast<const uint32_t*>(&Xb[g][kt * 16 + c * 2]);
            uint32_t b01 = *reinterpret_cast<const uint32_t*>(&Xb[g][kt * 16 + c * 2 + 8]);
            uint32_t b10 = *reinterpret_cast<const uint32_t*>(&Xb[g + 8][kt * 16 + c * 2]);
            uint32_t b11 = *reinterpret_cast<const uint32_t*>(&Xb[g + 8][kt * 16 + c * 2 + 8]);
            uint32_t b20 = *reinterpret_cast<const uint32_t*>(&Xb[g][(kt + 8) * 16 + c * 2]);
            uint32_t b21 = *reinterpret_cast<const uint32_t*>(&Xb[g][(kt + 8) * 16 + c * 2 + 8]);
            uint32_t b30 = *reinterpret_cast<const uint32_t*>(&Xb[g + 8][(kt + 8) * 16 + c * 2]);
            uint32_t b31 = *reinterpret_cast<const uint32_t*>(&Xb[g + 8][(kt + 8) * 16 + c * 2 + 8]);
            mma16816(d[0][0][0], ta[0][kt], b00, b01);
            mma16816(d[0][1][0], ta[1][kt], b00, b01);
            mma16816(d[0][0][1], ta[0][kt], b10, b11);
            mma16816(d[0][1][1], ta[1][kt], b10, b11);
            mma16816(d[1][0][0], ta[0][kt + 8], b20, b21);
            mma16816(d[1][1][0], ta[1][kt + 8], b20, b21);
            mma16816(d[1][0][1], ta[0][kt + 8], b30, b31);
            mma16816(d[1][1][1], ta[1][kt + 8], b30, b31);
        }

        // ---- fragment-space: v = D*p, fused sum + entropy reduction ----
        // local chunk slot li: 0 -> n=2c, 1 -> 2c+1, 2 -> 2c+8, 3 -> 2c+9
        float v[2][2][4];
        float sv[4] = {0.f, 0.f, 0.f, 0.f};
        float su[4] = {0.f, 0.f, 0.f, 0.f};
        #pragma unroll
        for (int mt = 0; mt < 2; ++mt) {
            #pragma unroll
            for (int nt = 0; nt < 2; ++nt) {
                const int r  = w * 32 + mt * 16 + g;
                const int n0 = c * 2 + nt * 8;
                float a0 = d[0][mt][nt][0] + d[1][mt][nt][0];
                float a1 = d[0][mt][nt][1] + d[1][mt][nt][1];
                float a2 = d[0][mt][nt][2] + d[1][mt][nt][2];
                float a3 = d[0][mt][nt][3] + d[1][mt][nt][3];
                float v0 = a0 * P2[buf][n0][r];
                float v1 = a1 * P2[buf][n0 + 1][r];
                float v2 = a2 * P2[buf][n0][r + 8];
                float v3 = a3 * P2[buf][n0 + 1][r + 8];
                v[mt][nt][0] = v0; v[mt][nt][1] = v1;
                v[mt][nt][2] = v2; v[mt][nt][3] = v3;
                sv[nt * 2]     += v0 + v2;
                sv[nt * 2 + 1] += v1 + v3;
                su[nt * 2]     += v0 * __logf(v0 + 1e-30f) + v2 * __logf(v2 + 1e-30f);
                su[nt * 2 + 1] += v1 * __logf(v1 + 1e-30f) + v3 * __logf(v3 + 1e-30f);
            }
        }
        // reduce over g (lanes sharing c): xor offsets 4, 8, 16
        #pragma unroll
        for (int off = 4; off <= 16; off <<= 1) {
            #pragma unroll
            for (int li = 0; li < 4; ++li) {
                sv[li] += __shfl_xor_sync(~0u, sv[li], off);
                su[li] += __shfl_xor_sync(~0u, su[li], off);
            }
        }
        if (lane < 4) {   // g == 0, c = lane
            #pragma unroll
            for (int li = 0; li < 4; ++li) {
                int n = lane * 2 + (li & 1) + (li >> 1) * 8;
                wsum[w][n] = sv[li];
                esum[w][n] = su[li];
            }
        }
        __syncthreads();   // B1: wsum/esum visible; all Xb MMA reads done

        // ---- per-warp: chunk sums -> inv, then normalize in fragment space ----
        float invl = 0.f, lSl = 0.f, El = 0.f;
        if (lane < CPB) {
            float S = 0.f, E = 0.f;
            #pragma unroll
            for (int ww = 0; ww < 8; ++ww) { S += wsum[ww][lane]; E += esum[ww][lane]; }
            invl = __fdividef(1.0f, S);
            lSl  = __logf(S);
            El   = E;
        }
        float inv[4];
        #pragma unroll
        for (int li = 0; li < 4; ++li)
            inv[li] = __shfl_sync(~0u, invl, c * 2 + (li & 1) + (li >> 1) * 8);

        #pragma unroll
        for (int mt = 0; mt < 2; ++mt) {
            #pragma unroll
            for (int nt = 0; nt < 2; ++nt) {
                #pragma unroll
                for (int j = 0; j < 4; ++j) {
                    const int n  = c * 2 + nt * 8 + (j & 1);
                    const int r  = w * 32 + mt * 16 + g + (j >> 1) * 8;
                    const int li = nt * 2 + (j & 1);
                    float sn = v[mt][nt][j] * inv[li];
                    if (s >= WARM) {
                        int gc = gc0 + n;
                        int t  = chunk_tb(gc) + s;
                        if (t < chunk_tl(gc)) out[(size_t)t * DIM + r] = sn;
                    }
                    // chunk 0 (global) warm/real boundary: reset to uniform
                    if (blockIdx.x == 0 && n == 0 && s == WARM - 1) sn = 0.00390625f;
                    Xb[n][r] = __bfloat16_as_ushort(__float2bfloat16(sn));
                }
            }
        }

        // entropy = log S - (sum v log v)/S
        if (w == 0 && lane < CPB && s >= WARM) {
            int gc = gc0 + lane;
            int t  = chunk_tb(gc) + s;
            if (t < chunk_tl(gc))
                out[(size_t)SEQ_LEN * DIM + t] = lSl - El * invl;
        }

        // stage next step's observations
        #pragma unroll
        for (int n = 0; n < CPB; ++n)
            P2[buf ^ 1][n][tid] = pnx[n];

        __syncthreads();   // B2: Xb + P2[next] visible for next step
    }
}

extern "C" void kernel_launch(void* const* d_in, const int* in_sizes, int n_in,
                              void* d_out, int out_size)
{
    const float* probs = (const float*)d_in[0];   // (65536, 256)
    const float* T     = (const float*)d_in[1];   // (256, 256)
    float* out         = (float*)d_out;           // 65536*256 probs, then 65536 entropy

    prior_layer_hmma<<<GRID, 256>>>(probs, T, out);
}